// round 3
// baseline (speedup 1.0000x reference)
#include <cuda_runtime.h>
#include <math.h>

// ---------------------------------------------------------------------------
// Problem shape (fixed by the reference setup_inputs)
// ---------------------------------------------------------------------------
#define BB 4
#define SS 4096
#define DD 1024
#define HH 4096
#define MM (BB * SS)          // 16384 rows
#define NCHUNK 64
#define CHLEN (SS / NCHUNK)   // 64
#define NCH (BB * DD)         // 4096 scan channels

// ---------------------------------------------------------------------------
// Scratch (static __device__ arrays: no allocation at runtime)
// ---------------------------------------------------------------------------
__device__ float g_normed[(size_t)MM * DD];   // RMS(x) / RMS(x1)
__device__ float g_k     [(size_t)MM * DD];   // k, later reused for r*wkv
__device__ float g_kv    [(size_t)MM * DD];   // k*v
__device__ float g_r     [(size_t)MM * DD];   // sigmoid(r)
__device__ float g_x1    [(size_t)MM * DD];   // x + mixer_scale*mixer_out
__device__ float g_h2    [(size_t)MM * HH];   // leaky(z)^2
__device__ float g_carry  [NCHUNK * NCH];
__device__ float g_carryin[NCHUNK * NCH];

// ---------------------------------------------------------------------------
// RMS norm: one block per row, 256 threads, 4 floats/thread (D=1024)
// ---------------------------------------------------------------------------
__global__ void rms_kernel(const float* __restrict__ x, float* __restrict__ out)
{
    const int row = blockIdx.x;
    const float4* xr = (const float4*)(x + (size_t)row * DD);
    float4 a = xr[threadIdx.x];
    float ss = a.x * a.x + a.y * a.y + a.z * a.z + a.w * a.w;
    #pragma unroll
    for (int o = 16; o > 0; o >>= 1)
        ss += __shfl_xor_sync(0xffffffffu, ss, o);
    __shared__ float sred[8];
    __shared__ float s_scale;
    if ((threadIdx.x & 31) == 0) sred[threadIdx.x >> 5] = ss;
    __syncthreads();
    if (threadIdx.x == 0) {
        float t = 0.f;
        #pragma unroll
        for (int i = 0; i < 8; i++) t += sred[i];
        s_scale = rsqrtf(t * (1.0f / DD) + 1e-6f);
    }
    __syncthreads();
    const float sc = s_scale;
    float4 o4 = make_float4(a.x * sc, a.y * sc, a.z * sc, a.w * sc);
    ((float4*)(out + (size_t)row * DD))[threadIdx.x] = o4;
}

// ---------------------------------------------------------------------------
// SGEMM: C[M,N] = epi( A[M,K] @ W[N,K]^T )
// 128x128 tile, BK=8, 256 threads, 8x8 per thread, float4 smem fragments.
// Epilogues:
//   0 = plain            C = z
//   1 = mul              C = z * aux           (aux: [M,N])   -> kv = v*k
//   2 = sigmoid          C = 1/(1+exp(-z))
//   3 = leaky(0.5)^2     t = z>0 ? z : 0.5z;  C = t*t
//   4 = residual         C = aux + scale[col]*z
// ---------------------------------------------------------------------------
template <int EPI>
__global__ __launch_bounds__(256, 2)
void sgemm_kernel(const float* __restrict__ A, const float* __restrict__ W,
                  float* __restrict__ C, int M, int N, int K,
                  const float* __restrict__ aux, const float* __restrict__ scale)
{
    __shared__ float As[8][128];
    __shared__ float Bs[8][128];

    const int tid = threadIdx.x;
    const int loadRow = tid >> 1;          // 0..127
    const int loadCol = (tid & 1) << 2;    // 0 or 4
    const size_t aBase = (size_t)(blockIdx.y * 128 + loadRow) * K + loadCol;
    const size_t wBase = (size_t)(blockIdx.x * 128 + loadRow) * K + loadCol;
    const int tx = (tid & 15) << 3;        // col offset in tile, 0..120
    const int ty = (tid >> 4) << 3;        // row offset in tile, 0..120

    float acc[8][8];
    #pragma unroll
    for (int i = 0; i < 8; i++)
        #pragma unroll
        for (int j = 0; j < 8; j++) acc[i][j] = 0.f;

    for (int k0 = 0; k0 < K; k0 += 8) {
        float4 a4 = *(const float4*)(A + aBase + k0);
        float4 b4 = *(const float4*)(W + wBase + k0);
        As[loadCol + 0][loadRow] = a4.x;
        As[loadCol + 1][loadRow] = a4.y;
        As[loadCol + 2][loadRow] = a4.z;
        As[loadCol + 3][loadRow] = a4.w;
        Bs[loadCol + 0][loadRow] = b4.x;
        Bs[loadCol + 1][loadRow] = b4.y;
        Bs[loadCol + 2][loadRow] = b4.z;
        Bs[loadCol + 3][loadRow] = b4.w;
        __syncthreads();
        #pragma unroll
        for (int kk = 0; kk < 8; kk++) {
            // float4 fragment loads: LDS.128, conflict-free phases
            float4 a0 = *(const float4*)&As[kk][ty];
            float4 a1 = *(const float4*)&As[kk][ty + 4];
            float4 b0 = *(const float4*)&Bs[kk][tx];
            float4 b1 = *(const float4*)&Bs[kk][tx + 4];
            float ar[8] = {a0.x, a0.y, a0.z, a0.w, a1.x, a1.y, a1.z, a1.w};
            float br[8] = {b0.x, b0.y, b0.z, b0.w, b1.x, b1.y, b1.z, b1.w};
            #pragma unroll
            for (int i = 0; i < 8; i++)
                #pragma unroll
                for (int j = 0; j < 8; j++)
                    acc[i][j] += ar[i] * br[j];
        }
        __syncthreads();
    }

    const int rowBase = blockIdx.y * 128 + ty;
    const int colBase = blockIdx.x * 128 + tx;
    #pragma unroll
    for (int i = 0; i < 8; i++) {
        const size_t ro = (size_t)(rowBase + i) * N + colBase;
        #pragma unroll
        for (int j = 0; j < 8; j++) {
            float z = acc[i][j];
            float o;
            if (EPI == 0) {
                o = z;
            } else if (EPI == 1) {
                o = z * aux[ro + j];
            } else if (EPI == 2) {
                o = 1.0f / (1.0f + expf(-z));
            } else if (EPI == 3) {
                float t = z > 0.f ? z : 0.5f * z;
                o = t * t;
            } else {
                o = aux[ro + j] + scale[colBase + j] * z;
            }
            C[ro + j] = o;
        }
    }
}

// ---------------------------------------------------------------------------
// Chunked linear scan:  s_t = ew*s_{t-1} + kv_t ;  wkv_t = s_{t-1} + eu*kv_t
// Pass 1: per (chunk, channel) carry-out with zero carry-in.
// Pass 2: per channel, serial scan over NCHUNK carries (multiplier ew^CHLEN).
// Pass 3: per (chunk, channel) recompute with carry-in, write r*wkv.
// ---------------------------------------------------------------------------
__global__ void scan_pass1(const float* __restrict__ kv,
                           const float* __restrict__ td,
                           float* __restrict__ carry)
{
    const int idx = blockIdx.x * blockDim.x + threadIdx.x; // c*NCH + b*DD + d
    const int ch = idx & (NCH - 1);
    const int c  = idx >> 12;                // NCH = 4096 = 2^12
    const int d  = ch & (DD - 1);
    const int b  = ch >> 10;                 // DD = 1024 = 2^10
    const float ew = expf(-expf(td[d]));
    const float* p = kv + ((size_t)b * SS + (size_t)c * CHLEN) * DD + d;
    float s = 0.f;
    #pragma unroll 8
    for (int t = 0; t < CHLEN; t++)
        s = ew * s + p[t * DD];
    carry[idx] = s;
}

__global__ void scan_pass2(const float* __restrict__ carry,
                           float* __restrict__ carryin,
                           const float* __restrict__ td)
{
    const int ch = blockIdx.x * blockDim.x + threadIdx.x;  // 0..NCH-1
    const int d = ch & (DD - 1);
    const float ew = expf(-expf(td[d]));
    float ewL = ew;
    #pragma unroll
    for (int i = 0; i < 6; i++) ewL *= ewL;  // ew^64 = ew^CHLEN
    float s = 0.f;
    for (int c = 0; c < NCHUNK; c++) {
        carryin[c * NCH + ch] = s;
        s = ewL * s + carry[c * NCH + ch];
    }
}

__global__ void scan_pass3(const float* __restrict__ kv,
                           const float* __restrict__ r,
                           const float* __restrict__ td,
                           const float* __restrict__ tf,
                           const float* __restrict__ carryin,
                           float* __restrict__ rw)
{
    const int idx = blockIdx.x * blockDim.x + threadIdx.x;
    const int ch = idx & (NCH - 1);
    const int c  = idx >> 12;
    const int d  = ch & (DD - 1);
    const int b  = ch >> 10;
    const float ew = expf(-expf(td[d]));
    const float eu = expf(tf[d]);
    float s = carryin[idx];
    const size_t base = ((size_t)b * SS + (size_t)c * CHLEN) * DD + d;
    #pragma unroll 8
    for (int t = 0; t < CHLEN; t++) {
        const size_t o = base + (size_t)t * DD;
        float kvt = kv[o];
        float wkv = s + eu * kvt;
        rw[o] = r[o] * wkv;
        s = ew * s + kvt;
    }
}

// ---------------------------------------------------------------------------
// Launch
// ---------------------------------------------------------------------------
static float* symptr(const void* sym)
{
    void* p = nullptr;
    cudaGetSymbolAddress(&p, sym);
    return (float*)p;
}

extern "C" void kernel_launch(void* const* d_in, const int* in_sizes, int n_in,
                              void* d_out, int out_size)
{
    const float* x      = (const float*)d_in[0];
    const float* Wk     = (const float*)d_in[1];
    const float* Wv     = (const float*)d_in[2];
    const float* Wr     = (const float*)d_in[3];
    const float* Wo     = (const float*)d_in[4];
    const float* td     = (const float*)d_in[5];   // time_decay
    const float* tf     = (const float*)d_in[6];   // time_first
    const float* mxs    = (const float*)d_in[7];   // mixer_scale
    const float* Wfc    = (const float*)d_in[8];
    const float* Wmlp   = (const float*)d_in[9];
    const float* mls    = (const float*)d_in[10];  // mlp_scale
    float* out = (float*)d_out;

    float* normed  = symptr(g_normed);
    float* kbuf    = symptr(g_k);
    float* kvbuf   = symptr(g_kv);
    float* rbuf    = symptr(g_r);
    float* x1      = symptr(g_x1);
    float* h2      = symptr(g_h2);
    float* carry   = symptr(g_carry);
    float* carryin = symptr(g_carryin);

    const dim3 gD(DD / 128, MM / 128);   // N=1024 GEMMs
    const dim3 gH(HH / 128, MM / 128);   // N=4096 GEMM

    // 1. normed = RMS(x)
    rms_kernel<<<MM, 256>>>(x, normed);
    // 2. k = normed @ Wk^T
    sgemm_kernel<0><<<gD, 256>>>(normed, Wk, kbuf, MM, DD, DD, nullptr, nullptr);
    // 3. kv = (normed @ Wv^T) * k
    sgemm_kernel<1><<<gD, 256>>>(normed, Wv, kvbuf, MM, DD, DD, kbuf, nullptr);
    // 4. r = sigmoid(normed @ Wr^T)
    sgemm_kernel<2><<<gD, 256>>>(normed, Wr, rbuf, MM, DD, DD, nullptr, nullptr);
    // 5-7. chunked scan; rw = r * wkv  (written into kbuf)
    scan_pass1<<<(NCHUNK * NCH) / 256, 256>>>(kvbuf, td, carry);
    scan_pass2<<<NCH / 256, 256>>>(carry, carryin, td);
    scan_pass3<<<(NCHUNK * NCH) / 256, 256>>>(kvbuf, rbuf, td, tf, carryin, kbuf);
    // 8. x1 = x + mixer_scale * (rw @ Wo^T)
    sgemm_kernel<4><<<gD, 256>>>(kbuf, Wo, x1, MM, DD, DD, x, mxs);
    // 9. normed = RMS(x1)
    rms_kernel<<<MM, 256>>>(x1, normed);
    // 10. h2 = leaky(normed @ Wfc^T, 0.5)^2
    sgemm_kernel<3><<<gH, 256>>>(normed, Wfc, h2, MM, HH, DD, nullptr, nullptr);
    // 11. out = x1 + mlp_scale * (h2 @ Wmlp^T)
    sgemm_kernel<4><<<gD, 256>>>(h2, Wmlp, out, MM, DD, HH, x1, mls);
}

// round 5
// speedup vs baseline: 2.3371x; 2.3371x over previous
#include <cuda_runtime.h>
#include <cuda_bf16.h>
#include <cstdint>
#include <math.h>

// ---------------------------------------------------------------------------
// Shapes
// ---------------------------------------------------------------------------
#define BB 4
#define SS 4096
#define DD 1024
#define HH 4096
#define MM (BB * SS)          // 16384
#define NCHUNK 64
#define CHLEN (SS / NCHUNK)   // 64
#define NCH (BB * DD)         // 4096

// GEMM tiling
#define BM 128
#define BN 128
#define BK 32
#define BKP 40                // padded K stride (elems): 80B = 20 banks, conflict-free
#define TILE_E (BM * BKP)     // 5120 elems per tile copy
#define STAGE_B (4 * TILE_E * 2)   // Ah,Al,Bh,Bl  = 40960 bytes
#define SMEMSZ (2 * STAGE_B)       // 81920 bytes

// ---------------------------------------------------------------------------
// Scratch (__device__ globals; no runtime allocation)
// ---------------------------------------------------------------------------
__device__ float    g_k  [(size_t)MM * DD];
__device__ float    g_kv [(size_t)MM * DD];
__device__ float    g_r  [(size_t)MM * DD];
__device__ float    g_x1 [(size_t)MM * DD];
__device__ float    g_carry  [NCHUNK * NCH];
__device__ float    g_carryin[NCHUNK * NCH];
// bf16 split pairs (flat row-major, packed 2 elems per u32)
__device__ uint32_t g_actH[(size_t)MM * DD / 2];
__device__ uint32_t g_actL[(size_t)MM * DD / 2];
__device__ uint32_t g_h2H [(size_t)MM * HH / 2];
__device__ uint32_t g_h2L [(size_t)MM * HH / 2];
__device__ uint32_t g_wH[4][DD * DD / 2];     // Wk,Wv,Wr,Wo
__device__ uint32_t g_wL[4][DD * DD / 2];
__device__ uint32_t g_wfcH [HH * DD / 2];
__device__ uint32_t g_wfcL [HH * DD / 2];
__device__ uint32_t g_wmlpH[DD * HH / 2];
__device__ uint32_t g_wmlpL[DD * HH / 2];

// ---------------------------------------------------------------------------
// Small helpers
// ---------------------------------------------------------------------------
__device__ __forceinline__ uint32_t smem_u32(const void* p)
{
    uint32_t a;
    asm("{ .reg .u64 t; cvta.to.shared.u64 t, %1; cvt.u32.u64 %0, t; }"
        : "=r"(a) : "l"(p));
    return a;
}

__device__ __forceinline__ void cp16(uint32_t dst, const void* src)
{
    asm volatile("cp.async.cg.shared.global [%0], [%1], 16;"
                 :: "r"(dst), "l"(src) : "memory");
}
__device__ __forceinline__ void cp_commit()
{
    asm volatile("cp.async.commit_group;" ::: "memory");
}
template <int N>
__device__ __forceinline__ void cp_wait()
{
    asm volatile("cp.async.wait_group %0;" :: "n"(N) : "memory");
}

__device__ __forceinline__ void mma16816(float* c, const uint32_t* a, const uint32_t* b)
{
    asm volatile(
        "mma.sync.aligned.m16n8k16.row.col.f32.bf16.bf16.f32 "
        "{%0,%1,%2,%3}, {%4,%5,%6,%7}, {%8,%9}, {%0,%1,%2,%3};"
        : "+f"(c[0]), "+f"(c[1]), "+f"(c[2]), "+f"(c[3])
        : "r"(a[0]), "r"(a[1]), "r"(a[2]), "r"(a[3]), "r"(b[0]), "r"(b[1]));
}

__device__ __forceinline__ uint32_t pack_hi(float x, float y,
                                            float& rx, float& ry)
{
    __nv_bfloat16 hx = __float2bfloat16(x);
    __nv_bfloat16 hy = __float2bfloat16(y);
    rx = x - __bfloat162float(hx);
    ry = y - __bfloat162float(hy);
    __nv_bfloat162 p = __halves2bfloat162(hx, hy);
    return *reinterpret_cast<uint32_t*>(&p);
}
__device__ __forceinline__ uint32_t pack_bf(float x, float y)
{
    __nv_bfloat162 p = __halves2bfloat162(__float2bfloat16(x), __float2bfloat16(y));
    return *reinterpret_cast<uint32_t*>(&p);
}

// ---------------------------------------------------------------------------
// split_flat: fp32 -> (hi, lo) bf16 pairs, flat
// ---------------------------------------------------------------------------
__global__ void split_flat(const float* __restrict__ src,
                           uint32_t* __restrict__ hi, uint32_t* __restrict__ lo)
{
    const size_t i = (size_t)blockIdx.x * 256 + threadIdx.x;   // per 2 elems
    float2 v = ((const float2*)src)[i];
    float rx, ry;
    hi[i] = pack_hi(v.x, v.y, rx, ry);
    lo[i] = pack_bf(rx, ry);
}

// ---------------------------------------------------------------------------
// rms_split: RMS-normalize a row and emit split bf16 pairs directly
// ---------------------------------------------------------------------------
__global__ void rms_split(const float* __restrict__ x,
                          uint32_t* __restrict__ hi, uint32_t* __restrict__ lo)
{
    const int row = blockIdx.x;
    const float4 a = ((const float4*)(x + (size_t)row * DD))[threadIdx.x];
    float ss = a.x * a.x + a.y * a.y + a.z * a.z + a.w * a.w;
    #pragma unroll
    for (int o = 16; o > 0; o >>= 1) ss += __shfl_xor_sync(0xffffffffu, ss, o);
    __shared__ float sred[8];
    __shared__ float s_scale;
    if ((threadIdx.x & 31) == 0) sred[threadIdx.x >> 5] = ss;
    __syncthreads();
    if (threadIdx.x == 0) {
        float t = 0.f;
        #pragma unroll
        for (int i = 0; i < 8; i++) t += sred[i];
        s_scale = rsqrtf(t * (1.0f / DD) + 1e-6f);
    }
    __syncthreads();
    const float sc = s_scale;
    const size_t u = (size_t)row * (DD / 2) + 2 * threadIdx.x;
    float rx, ry;
    uint32_t h0 = pack_hi(a.x * sc, a.y * sc, rx, ry);
    uint32_t l0 = pack_bf(rx, ry);
    uint32_t h1 = pack_hi(a.z * sc, a.w * sc, rx, ry);
    uint32_t l1 = pack_bf(rx, ry);
    hi[u] = h0; hi[u + 1] = h1;
    lo[u] = l0; lo[u + 1] = l1;
}

// ---------------------------------------------------------------------------
// bf16 split-2 GEMM via mma.sync:  C[M,N] = epi( A[M,K] @ W[N,K]^T )
// A,B given as (hi,lo) bf16 pair arrays, flat row-major (packed u32 x2 elems).
// grid = (N/128, M/128), 256 threads (8 warps, 2x4), 64x32 per warp.
// EPI: 0 plain | 1 z*aux | 2 sigmoid | 3 leaky(0.5)^2 -> split pairs | 4 aux+scale*z
// ---------------------------------------------------------------------------
template <int EPI>
__global__ __launch_bounds__(256)
void mma_gemm(const uint32_t* __restrict__ Ah, const uint32_t* __restrict__ Al,
              const uint32_t* __restrict__ Bh, const uint32_t* __restrict__ Bl,
              float* __restrict__ C, int Nw, int K,
              const float* __restrict__ aux, const float* __restrict__ scale,
              uint32_t* __restrict__ th, uint32_t* __restrict__ tl)
{
    extern __shared__ char smem[];
    const uint32_t sbase = smem_u32(smem);

    const int tid  = threadIdx.x;
    const int wid  = tid >> 5;
    const int lane = tid & 31;
    const int wm   = wid >> 2;           // 0..1
    const int wn   = wid & 3;            // 0..3
    const int g    = lane >> 2;          // 0..7
    const int tg   = lane & 3;           // 0..3

    const int m0 = blockIdx.y * BM;
    const int n0 = blockIdx.x * BN;

    // global row bases (in u32 pair units; K/2 pairs per row)
    const int Kp = K >> 1;
    const uint32_t* gAh = Ah + (size_t)m0 * Kp;
    const uint32_t* gAl = Al + (size_t)m0 * Kp;
    const uint32_t* gBh = Bh + (size_t)n0 * Kp;
    const uint32_t* gBl = Bl + (size_t)n0 * Kp;

    float acc[4][4][4];
    #pragma unroll
    for (int i = 0; i < 4; i++)
        #pragma unroll
        for (int j = 0; j < 4; j++)
            #pragma unroll
            for (int q = 0; q < 4; q++) acc[i][j][q] = 0.f;

    // loader: one stage = Ah | Al | Bh | Bl tiles of [128][BKP] bf16
    auto load_stage = [&](int st, int kt) {
        const int k0p = kt * (BK / 2);             // pair offset of chunk
        const uint32_t sb = sbase + st * STAGE_B;
        #pragma unroll
        for (int i = 0; i < 2; i++) {
            const int idx = tid + i * 256;         // 0..511
            const int row = idx >> 2;
            const int c4  = (idx & 3) * 4;         // pair col (4 pairs = 16B)
            const uint32_t doff = (uint32_t)(row * BKP + c4 * 2) * 2; // bytes
            const size_t  soff = (size_t)row * Kp + k0p + c4;
            cp16(sb + doff,                gAh + soff);
            cp16(sb + TILE_E * 2 + doff,   gAl + soff);
            cp16(sb + TILE_E * 4 + doff,   gBh + soff);
            cp16(sb + TILE_E * 6 + doff,   gBl + soff);
        }
        cp_commit();
    };

    const int NK = K / BK;
    load_stage(0, 0);

    for (int kt = 0; kt < NK; kt++) {
        const int st = kt & 1;
        if (kt + 1 < NK) {
            load_stage(st ^ 1, kt + 1);
            cp_wait<1>();
        } else {
            cp_wait<0>();
        }
        __syncthreads();

        const char* sb  = smem + st * STAGE_B;
        const uint16_t* tAh = (const uint16_t*)(sb);
        const uint16_t* tAl = (const uint16_t*)(sb + TILE_E * 2);
        const uint16_t* tBh = (const uint16_t*)(sb + TILE_E * 4);
        const uint16_t* tBl = (const uint16_t*)(sb + TILE_E * 6);

        #pragma unroll
        for (int ks = 0; ks < 2; ks++) {
            const int kb = ks * 16 + tg * 2;
            uint32_t ah[4][4], al[4][4], bh[4][2], bl[4][2];
            #pragma unroll
            for (int mi = 0; mi < 4; mi++) {
                const int r = wm * 64 + mi * 16 + g;
                const int o = r * BKP + kb;
                ah[mi][0] = *(const uint32_t*)(tAh + o);
                ah[mi][1] = *(const uint32_t*)(tAh + o + 8 * BKP);
                ah[mi][2] = *(const uint32_t*)(tAh + o + 8);
                ah[mi][3] = *(const uint32_t*)(tAh + o + 8 * BKP + 8);
                al[mi][0] = *(const uint32_t*)(tAl + o);
                al[mi][1] = *(const uint32_t*)(tAl + o + 8 * BKP);
                al[mi][2] = *(const uint32_t*)(tAl + o + 8);
                al[mi][3] = *(const uint32_t*)(tAl + o + 8 * BKP + 8);
            }
            #pragma unroll
            for (int ni = 0; ni < 4; ni++) {
                const int n = wn * 32 + ni * 8 + g;
                const int o = n * BKP + kb;
                bh[ni][0] = *(const uint32_t*)(tBh + o);
                bh[ni][1] = *(const uint32_t*)(tBh + o + 8);
                bl[ni][0] = *(const uint32_t*)(tBl + o);
                bl[ni][1] = *(const uint32_t*)(tBl + o + 8);
            }
            #pragma unroll
            for (int mi = 0; mi < 4; mi++)
                #pragma unroll
                for (int ni = 0; ni < 4; ni++) {
                    mma16816(acc[mi][ni], ah[mi], bh[ni]);
                    mma16816(acc[mi][ni], ah[mi], bl[ni]);
                    mma16816(acc[mi][ni], al[mi], bh[ni]);
                }
        }
        __syncthreads();
    }

    // ------------------ epilogue ------------------
    #pragma unroll
    for (int mi = 0; mi < 4; mi++) {
        #pragma unroll
        for (int ni = 0; ni < 4; ni++) {
            const int r  = m0 + wm * 64 + mi * 16 + g;
            const int c  = n0 + wn * 32 + ni * 8 + tg * 2;
            #pragma unroll
            for (int half = 0; half < 2; half++) {
                const int rr = r + half * 8;
                float zx = acc[mi][ni][2 * half + 0];
                float zy = acc[mi][ni][2 * half + 1];
                const size_t ro = (size_t)rr * Nw + c;
                if (EPI == 3) {
                    float ux = zx > 0.f ? zx : 0.5f * zx;
                    float uy = zy > 0.f ? zy : 0.5f * zy;
                    float vx = ux * ux, vy = uy * uy;
                    float rx2, ry2;
                    uint32_t h = pack_hi(vx, vy, rx2, ry2);
                    uint32_t l = pack_bf(rx2, ry2);
                    th[ro >> 1] = h;
                    tl[ro >> 1] = l;
                } else {
                    float ox, oy;
                    if (EPI == 0) {
                        ox = zx; oy = zy;
                    } else if (EPI == 1) {
                        float2 a = *(const float2*)(aux + ro);
                        ox = zx * a.x; oy = zy * a.y;
                    } else if (EPI == 2) {
                        ox = 1.f / (1.f + expf(-zx));
                        oy = 1.f / (1.f + expf(-zy));
                    } else {
                        float2 a = *(const float2*)(aux + ro);
                        float2 s = *(const float2*)(scale + c);
                        ox = a.x + s.x * zx; oy = a.y + s.y * zy;
                    }
                    *(float2*)(C + ro) = make_float2(ox, oy);
                }
            }
        }
    }
}

// ---------------------------------------------------------------------------
// Chunked linear scan (3 passes)
// ---------------------------------------------------------------------------
__global__ void scan_pass1(const float* __restrict__ kv, const float* __restrict__ td,
                           float* __restrict__ carry)
{
    const int idx = blockIdx.x * blockDim.x + threadIdx.x;
    const int ch = idx & (NCH - 1);
    const int c  = idx >> 12;
    const int d  = ch & (DD - 1);
    const int b  = ch >> 10;
    const float ew = expf(-expf(td[d]));
    const float* p = kv + ((size_t)b * SS + (size_t)c * CHLEN) * DD + d;
    float s = 0.f;
    #pragma unroll 8
    for (int t = 0; t < CHLEN; t++) s = ew * s + p[t * DD];
    carry[idx] = s;
}

__global__ void scan_pass2(const float* __restrict__ carry, float* __restrict__ carryin,
                           const float* __restrict__ td)
{
    const int ch = blockIdx.x * blockDim.x + threadIdx.x;
    const int d = ch & (DD - 1);
    const float ew = expf(-expf(td[d]));
    float ewL = ew;
    #pragma unroll
    for (int i = 0; i < 6; i++) ewL *= ewL;   // ew^64
    float s = 0.f;
    for (int c = 0; c < NCHUNK; c++) {
        carryin[c * NCH + ch] = s;
        s = ewL * s + carry[c * NCH + ch];
    }
}

__global__ void scan_pass3(const float* __restrict__ kv, const float* __restrict__ r,
                           const float* __restrict__ td, const float* __restrict__ tf,
                           const float* __restrict__ carryin, float* __restrict__ rw)
{
    const int idx = blockIdx.x * blockDim.x + threadIdx.x;
    const int ch = idx & (NCH - 1);
    const int c  = idx >> 12;
    const int d  = ch & (DD - 1);
    const int b  = ch >> 10;
    const float ew = expf(-expf(td[d]));
    const float eu = expf(tf[d]);
    float s = carryin[idx];
    const size_t base = ((size_t)b * SS + (size_t)c * CHLEN) * DD + d;
    #pragma unroll 8
    for (int t = 0; t < CHLEN; t++) {
        const size_t o = base + (size_t)t * DD;
        float kvt = kv[o];
        rw[o] = r[o] * (s + eu * kvt);
        s = ew * s + kvt;
    }
}

// ---------------------------------------------------------------------------
// Launch
// ---------------------------------------------------------------------------
static void* symptr(const void* sym)
{
    void* p = nullptr;
    cudaGetSymbolAddress(&p, sym);
    return p;
}

extern "C" void kernel_launch(void* const* d_in, const int* in_sizes, int n_in,
                              void* d_out, int out_size)
{
    const float* x    = (const float*)d_in[0];
    const float* Wk   = (const float*)d_in[1];
    const float* Wv   = (const float*)d_in[2];
    const float* Wr   = (const float*)d_in[3];
    const float* Wo   = (const float*)d_in[4];
    const float* td   = (const float*)d_in[5];
    const float* tf   = (const float*)d_in[6];
    const float* mxs  = (const float*)d_in[7];
    const float* Wfc  = (const float*)d_in[8];
    const float* Wmlp = (const float*)d_in[9];
    const float* mls  = (const float*)d_in[10];
    float* out = (float*)d_out;

    float* kbuf    = (float*)symptr(g_k);
    float* kvbuf   = (float*)symptr(g_kv);
    float* rbuf    = (float*)symptr(g_r);
    float* x1      = (float*)symptr(g_x1);
    float* carry   = (float*)symptr(g_carry);
    float* carryin = (float*)symptr(g_carryin);

    uint32_t* actH  = (uint32_t*)symptr(g_actH);
    uint32_t* actL  = (uint32_t*)symptr(g_actL);
    uint32_t* h2H   = (uint32_t*)symptr(g_h2H);
    uint32_t* h2L   = (uint32_t*)symptr(g_h2L);
    uint32_t* wH    = (uint32_t*)symptr(g_wH);
    uint32_t* wL    = (uint32_t*)symptr(g_wL);
    uint32_t* wfcH  = (uint32_t*)symptr(g_wfcH);
    uint32_t* wfcL  = (uint32_t*)symptr(g_wfcL);
    uint32_t* wmlpH = (uint32_t*)symptr(g_wmlpH);
    uint32_t* wmlpL = (uint32_t*)symptr(g_wmlpL);
    const size_t WP = (size_t)DD * DD / 2;      // u32 pairs per 1024x1024 weight

    cudaFuncSetAttribute(mma_gemm<0>, cudaFuncAttributeMaxDynamicSharedMemorySize, SMEMSZ);
    cudaFuncSetAttribute(mma_gemm<1>, cudaFuncAttributeMaxDynamicSharedMemorySize, SMEMSZ);
    cudaFuncSetAttribute(mma_gemm<2>, cudaFuncAttributeMaxDynamicSharedMemorySize, SMEMSZ);
    cudaFuncSetAttribute(mma_gemm<3>, cudaFuncAttributeMaxDynamicSharedMemorySize, SMEMSZ);
    cudaFuncSetAttribute(mma_gemm<4>, cudaFuncAttributeMaxDynamicSharedMemorySize, SMEMSZ);

    // weight splits (flat)
    split_flat<<<DD * DD / 512, 256>>>(Wk, wH + 0 * WP, wL + 0 * WP);
    split_flat<<<DD * DD / 512, 256>>>(Wv, wH + 1 * WP, wL + 1 * WP);
    split_flat<<<DD * DD / 512, 256>>>(Wr, wH + 2 * WP, wL + 2 * WP);
    split_flat<<<DD * DD / 512, 256>>>(Wo, wH + 3 * WP, wL + 3 * WP);
    split_flat<<<HH * DD / 512, 256>>>(Wfc,  wfcH,  wfcL);
    split_flat<<<DD * HH / 512, 256>>>(Wmlp, wmlpH, wmlpL);

    const dim3 gD(DD / BN, MM / BM);   // (8,128)
    const dim3 gH(HH / BN, MM / BM);   // (32,128)

    // ---- mixer ----
    rms_split<<<MM, 256>>>(x, actH, actL);
    mma_gemm<0><<<gD, 256, SMEMSZ>>>(actH, actL, wH + 0 * WP, wL + 0 * WP,
                                     kbuf, DD, DD, nullptr, nullptr, nullptr, nullptr);
    mma_gemm<1><<<gD, 256, SMEMSZ>>>(actH, actL, wH + 1 * WP, wL + 1 * WP,
                                     kvbuf, DD, DD, kbuf, nullptr, nullptr, nullptr);
    mma_gemm<2><<<gD, 256, SMEMSZ>>>(actH, actL, wH + 2 * WP, wL + 2 * WP,
                                     rbuf, DD, DD, nullptr, nullptr, nullptr, nullptr);
    scan_pass1<<<(NCHUNK * NCH) / 256, 256>>>(kvbuf, td, carry);
    scan_pass2<<<NCH / 256, 256>>>(carry, carryin, td);
    scan_pass3<<<(NCHUNK * NCH) / 256, 256>>>(kvbuf, rbuf, td, tf, carryin, kbuf);
    split_flat<<<(int)((size_t)MM * DD / 512), 256>>>(kbuf, actH, actL);
    mma_gemm<4><<<gD, 256, SMEMSZ>>>(actH, actL, wH + 3 * WP, wL + 3 * WP,
                                     x1, DD, DD, x, mxs, nullptr, nullptr);
    // ---- MLP ----
    rms_split<<<MM, 256>>>(x1, actH, actL);
    mma_gemm<3><<<gH, 256, SMEMSZ>>>(actH, actL, wfcH, wfcL,
                                     nullptr, HH, DD, nullptr, nullptr, h2H, h2L);
    mma_gemm<4><<<gD, 256, SMEMSZ>>>(h2H, h2L, wmlpH, wmlpL,
                                     out, DD, HH, x1, mls, nullptr, nullptr);
}